// round 3
// baseline (speedup 1.0000x reference)
#include <cuda_runtime.h>
#include <math.h>

#define Tn 1024
#define Bn 128
#define Nn 256
#define Dn 256

// ---------------- static device scratch ----------------
__device__ float g_XP[(size_t)Bn * Tn * 3072];   // [(b*T+t)][g*768+col]
__device__ float g_H [4 * Dn * Bn];              // [g][k][b]
__device__ float g_RH[4 * Dn * Bn];              // [g][k][b]
__device__ float g_Z [4 * Dn * Bn];              // [g][d][b]
__device__ unsigned g_bar[4];

// ---------------- init: H0, barrier reset, ci boundary zeros ----------------
__global__ void init_kernel(const float* __restrict__ ic_h0,
                            const float* __restrict__ ci_h0,
                            float* __restrict__ out) {
    int i = blockIdx.x * 256 + threadIdx.x;
    if (i < 4 * Dn * Bn) {
        int g = i / (Dn * Bn);
        int k = (i % (Dn * Bn)) / Bn;
        const float* h0 = (g < 2) ? ic_h0 : ci_h0;
        g_H[i] = h0[(g & 1) * Dn + k];
    }
    if (i < Bn * Dn) {
        int b = i / Dn, d = i % Dn;
        float* ci = out + 32768;
        ci[((size_t)b * Tn) * 512 + d] = 0.0f;                    // t=0 fwd half
        ci[((size_t)b * Tn + (Tn - 1)) * 512 + 256 + d] = 0.0f;   // t=T-1 bwd half
    }
    if (i < 4) g_bar[i] = 0u;
}

// ---------------- xproj SGEMM: g_XP = data @ [Wk_g] + b_g ----------------
// M=131072 (b*T+t), K=256, N=3072 (4 GRUs x 768). 128x128 tiles, 8x8/thread.
__global__ void __launch_bounds__(256) xproj_kernel(
    const float* __restrict__ X,
    const float* __restrict__ W0, const float* __restrict__ W1,
    const float* __restrict__ W2, const float* __restrict__ W3,
    const float* __restrict__ b0, const float* __restrict__ b1,
    const float* __restrict__ b2, const float* __restrict__ b3)
{
    __shared__ float As[8][128];
    __shared__ float Bs[8][128];

    const int n0 = blockIdx.x * 128;
    const int m0 = blockIdx.y * 128;
    const int g  = n0 / 768;
    const int nc = n0 - g * 768;
    const float* W    = (g == 0) ? W0 : (g == 1) ? W1 : (g == 2) ? W2 : W3;
    const float* bias = (g == 0) ? b0 : (g == 1) ? b1 : (g == 2) ? b2 : b3;

    const int t    = threadIdx.x;
    const int warp = t >> 5, lane = t & 31;
    const int row0 = (warp & 3) * 32 + (lane >> 3) * 8;
    const int col0 = (warp >> 2) * 64 + (lane & 7) * 8;

    const int am = t >> 1, ak = (t & 1) * 4;
    const int bk = t >> 5, bn = (t & 31) * 4;

    float acc[8][8];
    #pragma unroll
    for (int i = 0; i < 8; i++)
        #pragma unroll
        for (int j = 0; j < 8; j++) acc[i][j] = 0.0f;

    for (int k0 = 0; k0 < 256; k0 += 8) {
        float4 av = __ldg((const float4*)&X[(size_t)(m0 + am) * 256 + k0 + ak]);
        float4 bv = __ldg((const float4*)&W[(size_t)(k0 + bk) * 768 + nc + bn]);
        __syncthreads();
        As[ak + 0][am] = av.x; As[ak + 1][am] = av.y;
        As[ak + 2][am] = av.z; As[ak + 3][am] = av.w;
        *(float4*)&Bs[bk][bn] = bv;
        __syncthreads();

        #pragma unroll
        for (int kk = 0; kk < 8; ++kk) {
            float4 a0 = *(const float4*)&As[kk][row0];
            float4 a1 = *(const float4*)&As[kk][row0 + 4];
            float4 c0 = *(const float4*)&Bs[kk][col0];
            float4 c1 = *(const float4*)&Bs[kk][col0 + 4];
            float ar[8] = {a0.x, a0.y, a0.z, a0.w, a1.x, a1.y, a1.z, a1.w};
            float br[8] = {c0.x, c0.y, c0.z, c0.w, c1.x, c1.y, c1.z, c1.w};
            #pragma unroll
            for (int i = 0; i < 8; i++)
                #pragma unroll
                for (int j = 0; j < 8; j++)
                    acc[i][j] += ar[i] * br[j];
        }
    }

    float bb[8];
    #pragma unroll
    for (int j = 0; j < 8; j++) bb[j] = bias[nc + col0 + j];

    #pragma unroll
    for (int i = 0; i < 8; i++) {
        float4 v0 = make_float4(acc[i][0] + bb[0], acc[i][1] + bb[1],
                                acc[i][2] + bb[2], acc[i][3] + bb[3]);
        float4 v1 = make_float4(acc[i][4] + bb[4], acc[i][5] + bb[5],
                                acc[i][6] + bb[6], acc[i][7] + bb[7]);
        size_t off = (size_t)(m0 + row0 + i) * 3072 + n0 + col0;
        *(float4*)&g_XP[off]     = v0;
        *(float4*)&g_XP[off + 4] = v1;
    }
}

// ---------------- per-GRU grid barrier (32 CTAs each) ----------------
static __device__ __forceinline__ void gbar(int g, unsigned target) {
    __syncthreads();
    if (threadIdx.x == 0) {
        __threadfence();
        atomicAdd(&g_bar[g], 1u);
        while (*((volatile unsigned*)&g_bar[g]) < target) { }
        __threadfence();
    }
    __syncthreads();
}

// ---------------- persistent scan: 128 CTAs = 4 GRUs x 32 ----------------
// smem: Hs[256*128] | U1s[256*16] | U2s[256*8] | XPs[16*132]
#define HS_OFF  0
#define U1_OFF  32768
#define U2_OFF  (32768 + 4096)
#define XPS_OFF (32768 + 4096 + 2048)
#define SCAN_SMEM_BYTES ((32768 + 4096 + 2048 + 16 * 132) * 4)

__global__ void __launch_bounds__(256, 1) scan_kernel(
    const float* __restrict__ U0, const float* __restrict__ U1,
    const float* __restrict__ U2, const float* __restrict__ U3,
    float* __restrict__ out)
{
    extern __shared__ float sm[];
    float* Hs  = sm + HS_OFF;
    float* U1s = sm + U1_OFF;
    float* U2s = sm + U2_OFF;
    float* XPs = sm + XPS_OFF;

    const int g = blockIdx.x >> 5;
    const int c = blockIdx.x & 31;
    const int tid = threadIdx.x;
    const float* U = (g == 0) ? U0 : (g == 1) ? U1 : (g == 2) ? U2 : U3;

    // resident U slabs: 16 zr cols + 8 hh cols for this CTA
    for (int i = tid; i < Dn * 16; i += 256) {
        int k = i >> 4, j = i & 15;
        U1s[i] = U[k * 768 + c * 16 + j];
    }
    for (int i = tid; i < Dn * 8; i += 256) {
        int k = i >> 3, j = i & 7;
        U2s[i] = U[k * 768 + 512 + c * 8 + j];
    }

    const int j1 = tid >> 4;            // 0..15 : zr col within slab
    const int b1 = (tid & 15) * 8;      // 8 batch rows
    const int j2 = tid & 7;             // 0..7  : hh col within slab
    const int b2 = (tid >> 3) * 4;      // 4 batch rows
    const int gcol = c * 16 + j1;       // global zr col (0..511)
    const int d2 = c * 8 + j2;          // hh hidden index (0..255)

    float* myH  = g_H  + g * Dn * Bn;
    float* myRH = g_RH + g * Dn * Bn;
    float* myZ  = g_Z  + g * Dn * Bn;
    float* ci   = out + 32768;
    unsigned tgt = 0;
    __syncthreads();

    for (int s = 0; s < Tn; s++) {
        const int t = (g & 1) ? (Tn - 1 - s) : s;

        // ---- stage H and XP_zr ----
        for (int i = tid * 4; i < Dn * Bn; i += 1024)
            *(float4*)(Hs + i) = __ldcg((const float4*)(myH + i));
        {
            const float* xpz = g_XP + (size_t)t * 3072 + (size_t)g * 768 + c * 16;
            for (int i = tid; i < 2048; i += 256) {
                int bb = i >> 4, jj = i & 15;
                XPs[jj * 132 + bb] = __ldg(xpz + (size_t)bb * (Tn * 3072) + jj);
            }
        }
        __syncthreads();

        // ---- phase 1: zr pre-activation ----
        {
            float acc[8];
            #pragma unroll
            for (int ii = 0; ii < 8; ii++) acc[ii] = XPs[j1 * 132 + b1 + ii];
            #pragma unroll 4
            for (int k = 0; k < Dn; k++) {
                float u = U1s[k * 16 + j1];
                float4 h0 = *(const float4*)(Hs + k * 128 + b1);
                float4 h1 = *(const float4*)(Hs + k * 128 + b1 + 4);
                acc[0] += h0.x * u; acc[1] += h0.y * u;
                acc[2] += h0.z * u; acc[3] += h0.w * u;
                acc[4] += h1.x * u; acc[5] += h1.y * u;
                acc[6] += h1.z * u; acc[7] += h1.w * u;
            }
            if (c < 16) {   // z gate
                float4 z0, z1;
                z0.x = 1.f/(1.f+expf(-acc[0])); z0.y = 1.f/(1.f+expf(-acc[1]));
                z0.z = 1.f/(1.f+expf(-acc[2])); z0.w = 1.f/(1.f+expf(-acc[3]));
                z1.x = 1.f/(1.f+expf(-acc[4])); z1.y = 1.f/(1.f+expf(-acc[5]));
                z1.z = 1.f/(1.f+expf(-acc[6])); z1.w = 1.f/(1.f+expf(-acc[7]));
                __stcg((float4*)(myZ + gcol * 128 + b1), z0);
                __stcg((float4*)(myZ + gcol * 128 + b1 + 4), z1);
            } else {        // r gate -> r*h
                int d = gcol - 256;
                float4 r0, r1;
                r0.x = Hs[d*128+b1+0] / (1.f+expf(-acc[0]));
                r0.y = Hs[d*128+b1+1] / (1.f+expf(-acc[1]));
                r0.z = Hs[d*128+b1+2] / (1.f+expf(-acc[2]));
                r0.w = Hs[d*128+b1+3] / (1.f+expf(-acc[3]));
                r1.x = Hs[d*128+b1+4] / (1.f+expf(-acc[4]));
                r1.y = Hs[d*128+b1+5] / (1.f+expf(-acc[5]));
                r1.z = Hs[d*128+b1+6] / (1.f+expf(-acc[6]));
                r1.w = Hs[d*128+b1+7] / (1.f+expf(-acc[7]));
                __stcg((float4*)(myRH + d * 128 + b1), r0);
                __stcg((float4*)(myRH + d * 128 + b1 + 4), r1);
            }
        }
        tgt += 32;
        gbar(g, tgt);

        // ---- stage RH and XP_h ----
        for (int i = tid * 4; i < Dn * Bn; i += 1024)
            *(float4*)(Hs + i) = __ldcg((const float4*)(myRH + i));
        {
            const float* xph = g_XP + (size_t)t * 3072 + (size_t)g * 768 + 512 + c * 8;
            for (int i = tid; i < 1024; i += 256) {
                int bb = i >> 3, jj = i & 7;
                XPs[jj * 132 + bb] = __ldg(xph + (size_t)bb * (Tn * 3072) + jj);
            }
        }
        __syncthreads();

        // ---- phase 2: candidate + state update ----
        {
            float acc[4];
            #pragma unroll
            for (int ii = 0; ii < 4; ii++) acc[ii] = XPs[j2 * 132 + b2 + ii];
            #pragma unroll 4
            for (int k = 0; k < Dn; k++) {
                float u = U2s[k * 8 + j2];
                float4 h = *(const float4*)(Hs + k * 128 + b2);
                acc[0] += h.x * u; acc[1] += h.y * u;
                acc[2] += h.z * u; acc[3] += h.w * u;
            }
            float4 z4 = __ldcg((const float4*)(myZ + d2 * 128 + b2));
            float4 h4 = __ldcg((const float4*)(myH + d2 * 128 + b2));
            float zz[4] = {z4.x, z4.y, z4.z, z4.w};
            float hh[4] = {h4.x, h4.y, h4.z, h4.w};
            float hn[4];
            #pragma unroll
            for (int ii = 0; ii < 4; ii++) {
                float cand = tanhf(acc[ii]);
                float v = zz[ii] * hh[ii] + (1.0f - zz[ii]) * cand;
                hn[ii] = fminf(5.0f, fmaxf(-5.0f, v));
            }
            float4 o = make_float4(hn[0], hn[1], hn[2], hn[3]);
            __stcg((float4*)(myH + d2 * 128 + b2), o);

            if (g == 2 && s < Tn - 1) {         // ci_fwd -> t = s+1, ch = d2
                #pragma unroll
                for (int ii = 0; ii < 4; ii++)
                    ci[((size_t)(b2 + ii) * Tn + s + 1) * 512 + d2] = hn[ii];
            } else if (g == 3 && s < Tn - 1) {  // ci_bwd -> t = T-2-s, ch = 256+d2
                #pragma unroll
                for (int ii = 0; ii < 4; ii++)
                    ci[((size_t)(b2 + ii) * Tn + (Tn - 2 - s)) * 512 + 256 + d2] = hn[ii];
            }
        }
        tgt += 32;
        gbar(g, tgt);
    }
}

// ---------------- heads: ic_mean / ic_stddev ----------------
__global__ void __launch_bounds__(128) head_kernel(
    const float* __restrict__ Wm, const float* __restrict__ bm,
    const float* __restrict__ Wlv, const float* __restrict__ blv,
    float* __restrict__ out)
{
    __shared__ float hn[512];
    int b = blockIdx.x, m = threadIdx.x;
    for (int i = m; i < 512; i += 128)
        hn[i] = (i < 256) ? g_H[i * 128 + b] : g_H[Dn * Bn + (i - 256) * 128 + b];
    __syncthreads();
    float am = bm[m], alv = blv[m];
    for (int k = 0; k < 512; k++) {
        float h = hn[k];
        am  += h * Wm [k * 128 + m];
        alv += h * Wlv[k * 128 + m];
    }
    out[b * 128 + m] = am;
    out[16384 + b * 128 + m] = sqrtf(expf(alv) + 1e-4f);
}

// ---------------- launch ----------------
extern "C" void kernel_launch(void* const* d_in, const int* in_sizes, int n_in,
                              void* d_out, int out_size) {
    const float* data = (const float*)d_in[0];
    const float* icWf = (const float*)d_in[1];
    const float* icUf = (const float*)d_in[2];
    const float* icbf = (const float*)d_in[3];
    const float* icWb = (const float*)d_in[4];
    const float* icUb = (const float*)d_in[5];
    const float* icbb = (const float*)d_in[6];
    const float* ich0 = (const float*)d_in[7];
    const float* ciWf = (const float*)d_in[8];
    const float* ciUf = (const float*)d_in[9];
    const float* cibf = (const float*)d_in[10];
    const float* ciWb = (const float*)d_in[11];
    const float* ciUb = (const float*)d_in[12];
    const float* cibb = (const float*)d_in[13];
    const float* cih0 = (const float*)d_in[14];
    const float* Wm   = (const float*)d_in[15];
    const float* bm   = (const float*)d_in[16];
    const float* Wlv  = (const float*)d_in[17];
    const float* blv  = (const float*)d_in[18];
    float* out = (float*)d_out;

    cudaFuncSetAttribute(scan_kernel, cudaFuncAttributeMaxDynamicSharedMemorySize,
                         SCAN_SMEM_BYTES);

    init_kernel<<<512, 256>>>(ich0, cih0, out);

    dim3 grid(24, 1024);
    xproj_kernel<<<grid, 256>>>(data, icWf, icWb, ciWf, ciWb,
                                icbf, icbb, cibf, cibb);

    scan_kernel<<<128, 256, SCAN_SMEM_BYTES>>>(icUf, icUb, ciUf, ciUb, out);

    head_kernel<<<128, 128>>>(Wm, bm, Wlv, blv, out);
}

// round 4
// speedup vs baseline: 1.5926x; 1.5926x over previous
#include <cuda_runtime.h>
#include <math.h>

#define Tn 1024
#define Bn 128
#define Nn 256
#define Dn 256

// ---------------- static device scratch ----------------
__device__ float g_XP[(size_t)Bn * Tn * 3072];   // [(b*T+t)][g*768+col]
__device__ float g_H [4 * Dn * Bn];              // [g][k][b]
__device__ float g_RH[4 * Dn * Bn];              // [g][k][b]
__device__ unsigned g_bar[4];

// ---------------- f32x2 helpers ----------------
static __device__ __forceinline__ unsigned long long pk2(float lo, float hi) {
    unsigned long long r;
    asm("mov.b64 %0, {%1, %2};" : "=l"(r) : "f"(lo), "f"(hi));
    return r;
}
static __device__ __forceinline__ void up2(unsigned long long v, float& lo, float& hi) {
    asm("mov.b64 {%0, %1}, %2;" : "=f"(lo), "=f"(hi) : "l"(v));
}
static __device__ __forceinline__ void fma2(unsigned long long& d,
                                            unsigned long long a,
                                            unsigned long long b) {
    asm("fma.rn.f32x2 %0, %1, %2, %0;" : "+l"(d) : "l"(a), "l"(b));
}
static __device__ __forceinline__ void add2(unsigned long long& d, unsigned long long a) {
    asm("add.rn.f32x2 %0, %0, %1;" : "+l"(d) : "l"(a));
}
static __device__ __forceinline__ float sigf(float x) {
    return 1.0f / (1.0f + __expf(-x));
}
static __device__ __forceinline__ float tanhfast(float x) {
    float e = __expf(2.0f * x);
    return 1.0f - 2.0f / (e + 1.0f);
}

// ---------------- init ----------------
__global__ void init_kernel(const float* __restrict__ ic_h0,
                            const float* __restrict__ ci_h0,
                            float* __restrict__ out) {
    int i = blockIdx.x * 256 + threadIdx.x;
    if (i < 4 * Dn * Bn) {
        int g = i / (Dn * Bn);
        int k = (i % (Dn * Bn)) / Bn;
        const float* h0 = (g < 2) ? ic_h0 : ci_h0;
        g_H[i] = h0[(g & 1) * Dn + k];
    }
    if (i < Bn * Dn) {
        int b = i / Dn, d = i % Dn;
        float* ci = out + 32768;
        ci[((size_t)b * Tn) * 512 + d] = 0.0f;
        ci[((size_t)b * Tn + (Tn - 1)) * 512 + 256 + d] = 0.0f;
    }
    if (i < 4) g_bar[i] = 0u;
}

// ---------------- xproj SGEMM (unchanged) ----------------
__global__ void __launch_bounds__(256) xproj_kernel(
    const float* __restrict__ X,
    const float* __restrict__ W0, const float* __restrict__ W1,
    const float* __restrict__ W2, const float* __restrict__ W3,
    const float* __restrict__ b0, const float* __restrict__ b1,
    const float* __restrict__ b2, const float* __restrict__ b3)
{
    __shared__ float As[8][128];
    __shared__ float Bs[8][128];

    const int n0 = blockIdx.x * 128;
    const int m0 = blockIdx.y * 128;
    const int g  = n0 / 768;
    const int nc = n0 - g * 768;
    const float* W    = (g == 0) ? W0 : (g == 1) ? W1 : (g == 2) ? W2 : W3;
    const float* bias = (g == 0) ? b0 : (g == 1) ? b1 : (g == 2) ? b2 : b3;

    const int t    = threadIdx.x;
    const int warp = t >> 5, lane = t & 31;
    const int row0 = (warp & 3) * 32 + (lane >> 3) * 8;
    const int col0 = (warp >> 2) * 64 + (lane & 7) * 8;

    const int am = t >> 1, ak = (t & 1) * 4;
    const int bk = t >> 5, bn = (t & 31) * 4;

    float acc[8][8];
    #pragma unroll
    for (int i = 0; i < 8; i++)
        #pragma unroll
        for (int j = 0; j < 8; j++) acc[i][j] = 0.0f;

    for (int k0 = 0; k0 < 256; k0 += 8) {
        float4 av = __ldg((const float4*)&X[(size_t)(m0 + am) * 256 + k0 + ak]);
        float4 bv = __ldg((const float4*)&W[(size_t)(k0 + bk) * 768 + nc + bn]);
        __syncthreads();
        As[ak + 0][am] = av.x; As[ak + 1][am] = av.y;
        As[ak + 2][am] = av.z; As[ak + 3][am] = av.w;
        *(float4*)&Bs[bk][bn] = bv;
        __syncthreads();

        #pragma unroll
        for (int kk = 0; kk < 8; ++kk) {
            float4 a0 = *(const float4*)&As[kk][row0];
            float4 a1 = *(const float4*)&As[kk][row0 + 4];
            float4 c0 = *(const float4*)&Bs[kk][col0];
            float4 c1 = *(const float4*)&Bs[kk][col0 + 4];
            float ar[8] = {a0.x, a0.y, a0.z, a0.w, a1.x, a1.y, a1.z, a1.w};
            float br[8] = {c0.x, c0.y, c0.z, c0.w, c1.x, c1.y, c1.z, c1.w};
            #pragma unroll
            for (int i = 0; i < 8; i++)
                #pragma unroll
                for (int j = 0; j < 8; j++)
                    acc[i][j] += ar[i] * br[j];
        }
    }

    float bb[8];
    #pragma unroll
    for (int j = 0; j < 8; j++) bb[j] = bias[nc + col0 + j];

    #pragma unroll
    for (int i = 0; i < 8; i++) {
        float4 v0 = make_float4(acc[i][0] + bb[0], acc[i][1] + bb[1],
                                acc[i][2] + bb[2], acc[i][3] + bb[3]);
        float4 v1 = make_float4(acc[i][4] + bb[4], acc[i][5] + bb[5],
                                acc[i][6] + bb[6], acc[i][7] + bb[7]);
        size_t off = (size_t)(m0 + row0 + i) * 3072 + n0 + col0;
        *(float4*)&g_XP[off]     = v0;
        *(float4*)&g_XP[off + 4] = v1;
    }
}

// ---------------- per-GRU grid barrier ----------------
static __device__ __forceinline__ void gbar(int g, unsigned target) {
    __syncthreads();
    if (threadIdx.x == 0) {
        __threadfence();
        atomicAdd(&g_bar[g], 1u);
        while (*((volatile unsigned*)&g_bar[g]) < target) { }
        __threadfence();
    }
    __syncthreads();
}

// ---------------- scan smem layout (floats) ----------------
#define HS_OFF   0                       // 32768 : H / RH tile [256][128]
#define U1_OFF   32768                   // 4096  : zr U slab [256][16] (8 z cols | 8 r cols)
#define U2_OFF   (U1_OFF + 4096)         // 2048  : hh U slab [256][8]
#define XP1_OFF  (U2_OFF + 2048)         // 2080  : zr xproj [16][130]
#define XP2_OFF  (XP1_OFF + 2080)        // 1040  : hh xproj [8][130]
#define ZS_OFF   (XP2_OFF + 1040)        // 1024  : z gate [8][128]
#define HSV_OFF  (ZS_OFF + 1024)         // 1024  : saved old-H rows [8][128]
#define RS_OFF   (HSV_OFF + 1024)        // 2048  : k-split partials (1024 u64)
#define SCAN_SMEM_FLOATS (RS_OFF + 2048)
#define SCAN_SMEM_BYTES  (SCAN_SMEM_FLOATS * 4)

// ---------------- persistent scan: 128 CTAs = 4 GRUs x 32 ----------------
__global__ void __launch_bounds__(256, 1) scan_kernel(
    const float* __restrict__ U0, const float* __restrict__ U1,
    const float* __restrict__ U2, const float* __restrict__ U3,
    float* __restrict__ out)
{
    extern __shared__ float sm[];
    float* Hs   = sm + HS_OFF;
    float* U1s  = sm + U1_OFF;
    float* U2s  = sm + U2_OFF;
    float* XP1  = sm + XP1_OFF;
    float* XP2  = sm + XP2_OFF;
    float* Zs   = sm + ZS_OFF;
    float* HsSv = sm + HSV_OFF;
    unsigned long long* Rs = (unsigned long long*)(sm + RS_OFF);

    const int g   = blockIdx.x >> 5;
    const int c   = blockIdx.x & 31;
    const int tid = threadIdx.x;
    const float* U = (g == 0) ? U0 : (g == 1) ? U1 : (g == 2) ? U2 : U3;

    // U slabs: U1s[k][jj]: jj<8 -> z col c*8+jj ; jj>=8 -> r col 256+c*8+(jj-8)
    for (int i = tid; i < Dn * 16; i += 256) {
        int k = i >> 4, jj = i & 15;
        int col = (jj < 8) ? (c * 8 + jj) : (256 + c * 8 + (jj - 8));
        U1s[i] = U[k * 768 + col];
    }
    // U2s[k][jj]: hh col 512 + c*8 + jj
    for (int i = tid; i < Dn * 8; i += 256) {
        int k = i >> 3, jj = i & 7;
        U2s[i] = U[k * 768 + 512 + c * 8 + jj];
    }

    const int half = tid >> 7;        // k-split half
    const int lt   = tid & 127;
    const int kb   = half * 128;
    // phase1 tile: 8j x 2b
    const int jg1 = lt >> 6;          // 0 = z cols, 1 = r cols
    const int j01 = jg1 * 8;
    // phase2 tile: 4j x 2b
    const int jg2 = lt >> 6;
    const int j02 = jg2 * 4;
    const int b   = (lt & 63) * 2;

    float* myH  = g_H  + g * Dn * Bn;
    float* myRH = g_RH + g * Dn * Bn;
    float* ci   = out + 32768;
    unsigned tgt = 0;
    __syncthreads();

    for (int s = 0; s < Tn; s++) {
        const int t = (g & 1) ? (Tn - 1 - s) : s;
        const float* xp = g_XP + (size_t)t * 3072 + g * 768;

        // ================= stage: H + both xproj slices =================
        for (int i = tid * 4; i < Dn * Bn; i += 1024)
            *(float4*)(Hs + i) = __ldcg((const float4*)(myH + i));
        for (int i = tid; i < 2048; i += 256) {
            int bb_ = i >> 4, jj = i & 15;
            int col = (jj < 8) ? (c * 8 + jj) : (256 + c * 8 + (jj - 8));
            XP1[jj * 130 + bb_] = __ldg(xp + (size_t)bb_ * (Tn * 3072) + col);
        }
        for (int i = tid; i < 1024; i += 256) {
            int bb_ = i >> 3, jj = i & 7;
            XP2[jj * 130 + bb_] = __ldg(xp + (size_t)bb_ * (Tn * 3072) + 512 + c * 8 + jj);
        }
        __syncthreads();

        // ================= phase 1: zr pre-activation =================
        {
            unsigned long long acc[4][2];
            if (half == 0) {
                #pragma unroll
                for (int jp = 0; jp < 4; jp++)
                    #pragma unroll
                    for (int bb_ = 0; bb_ < 2; bb_++)
                        acc[jp][bb_] = pk2(XP1[(j01 + 2 * jp) * 130 + b + bb_],
                                           XP1[(j01 + 2 * jp + 1) * 130 + b + bb_]);
            } else {
                #pragma unroll
                for (int jp = 0; jp < 4; jp++) { acc[jp][0] = 0ULL; acc[jp][1] = 0ULL; }
            }

            #pragma unroll 4
            for (int k = kb; k < kb + 128; k++) {
                ulonglong2 ua = *(const ulonglong2*)(U1s + k * 16 + j01);
                ulonglong2 ub = *(const ulonglong2*)(U1s + k * 16 + j01 + 4);
                float2 h2 = *(const float2*)(Hs + k * 128 + b);
                unsigned long long h0d = pk2(h2.x, h2.x);
                unsigned long long h1d = pk2(h2.y, h2.y);
                fma2(acc[0][0], ua.x, h0d); fma2(acc[0][1], ua.x, h1d);
                fma2(acc[1][0], ua.y, h0d); fma2(acc[1][1], ua.y, h1d);
                fma2(acc[2][0], ub.x, h0d); fma2(acc[2][1], ub.x, h1d);
                fma2(acc[3][0], ub.y, h0d); fma2(acc[3][1], ub.y, h1d);
            }

            if (half) {
                #pragma unroll
                for (int jp = 0; jp < 4; jp++) {
                    Rs[lt * 8 + jp * 2]     = acc[jp][0];
                    Rs[lt * 8 + jp * 2 + 1] = acc[jp][1];
                }
            }
            __syncthreads();
            if (!half) {
                #pragma unroll
                for (int jp = 0; jp < 4; jp++) {
                    add2(acc[jp][0], Rs[lt * 8 + jp * 2]);
                    add2(acc[jp][1], Rs[lt * 8 + jp * 2 + 1]);
                }
                // epilogue: 16 values (j01..j01+7) x (b, b+1)
                #pragma unroll
                for (int jp = 0; jp < 4; jp++) {
                    float v00, v10, v01, v11;   // vXY: lane X (j offset), bb Y
                    up2(acc[jp][0], v00, v10);
                    up2(acc[jp][1], v01, v11);
                    int ja = j01 + 2 * jp, jb = ja + 1;
                    if (jg1 == 0) {  // z gate -> local smem
                        *(float2*)(Zs + ja * 128 + b) = make_float2(sigf(v00), sigf(v01));
                        *(float2*)(Zs + jb * 128 + b) = make_float2(sigf(v10), sigf(v11));
                    } else {         // r gate -> r*h -> global RH
                        int da = c * 8 + (ja - 8), db = c * 8 + (jb - 8);
                        float2 ha = *(const float2*)(Hs + da * 128 + b);
                        float2 hb = *(const float2*)(Hs + db * 128 + b);
                        __stcg((float2*)(myRH + da * 128 + b),
                               make_float2(sigf(v00) * ha.x, sigf(v01) * ha.y));
                        __stcg((float2*)(myRH + db * 128 + b),
                               make_float2(sigf(v10) * hb.x, sigf(v11) * hb.y));
                    }
                }
            }
        }
        tgt += 32;
        gbar(g, tgt);

        // ================= stage: save old-H rows, then RH =================
        for (int i = tid; i < 1024; i += 256)
            HsSv[i] = Hs[(c * 8 + (i >> 7)) * 128 + (i & 127)];
        __syncthreads();
        for (int i = tid * 4; i < Dn * Bn; i += 1024)
            *(float4*)(Hs + i) = __ldcg((const float4*)(myRH + i));
        __syncthreads();

        // ================= phase 2: candidate + update =================
        {
            unsigned long long acc[2][2];
            if (half == 0) {
                #pragma unroll
                for (int jp = 0; jp < 2; jp++)
                    #pragma unroll
                    for (int bb_ = 0; bb_ < 2; bb_++)
                        acc[jp][bb_] = pk2(XP2[(j02 + 2 * jp) * 130 + b + bb_],
                                           XP2[(j02 + 2 * jp + 1) * 130 + b + bb_]);
            } else {
                acc[0][0] = acc[0][1] = acc[1][0] = acc[1][1] = 0ULL;
            }

            #pragma unroll 4
            for (int k = kb; k < kb + 128; k++) {
                ulonglong2 u = *(const ulonglong2*)(U2s + k * 8 + j02);
                float2 h2 = *(const float2*)(Hs + k * 128 + b);
                unsigned long long h0d = pk2(h2.x, h2.x);
                unsigned long long h1d = pk2(h2.y, h2.y);
                fma2(acc[0][0], u.x, h0d); fma2(acc[0][1], u.x, h1d);
                fma2(acc[1][0], u.y, h0d); fma2(acc[1][1], u.y, h1d);
            }

            if (half) {
                #pragma unroll
                for (int jp = 0; jp < 2; jp++) {
                    Rs[lt * 4 + jp * 2]     = acc[jp][0];
                    Rs[lt * 4 + jp * 2 + 1] = acc[jp][1];
                }
            }
            __syncthreads();
            if (!half) {
                #pragma unroll
                for (int jp = 0; jp < 2; jp++) {
                    add2(acc[jp][0], Rs[lt * 4 + jp * 2]);
                    add2(acc[jp][1], Rs[lt * 4 + jp * 2 + 1]);
                }
                float hn[4][2];   // [j offset 0..3][bb]
                #pragma unroll
                for (int jp = 0; jp < 2; jp++) {
                    float v00, v10, v01, v11;
                    up2(acc[jp][0], v00, v10);
                    up2(acc[jp][1], v01, v11);
                    float xv[2][2] = {{v00, v01}, {v10, v11}};
                    #pragma unroll
                    for (int l = 0; l < 2; l++) {
                        int jj = j02 + 2 * jp + l;
                        #pragma unroll
                        for (int bb_ = 0; bb_ < 2; bb_++) {
                            float cand = tanhfast(xv[l][bb_]);
                            float z  = Zs[jj * 128 + b + bb_];
                            float ho = HsSv[jj * 128 + b + bb_];
                            float v  = z * ho + (1.0f - z) * cand;
                            hn[2 * jp + l][bb_] = fminf(5.0f, fmaxf(-5.0f, v));
                        }
                    }
                }
                // update H
                #pragma unroll
                for (int q = 0; q < 4; q++) {
                    int d = c * 8 + j02 + q;
                    __stcg((float2*)(myH + d * 128 + b),
                           make_float2(hn[q][0], hn[q][1]));
                }
                // ci outputs
                if (g >= 2 && s < Tn - 1) {
                    int d0 = c * 8 + j02;
                    #pragma unroll
                    for (int bb_ = 0; bb_ < 2; bb_++) {
                        float4 q4 = make_float4(hn[0][bb_], hn[1][bb_],
                                                hn[2][bb_], hn[3][bb_]);
                        size_t row = (g == 2)
                            ? ((size_t)(b + bb_) * Tn + s + 1) * 512 + d0
                            : ((size_t)(b + bb_) * Tn + (Tn - 2 - s)) * 512 + 256 + d0;
                        *(float4*)(ci + row) = q4;
                    }
                }
            }
        }
        tgt += 32;
        gbar(g, tgt);
    }
}

// ---------------- heads ----------------
__global__ void __launch_bounds__(128) head_kernel(
    const float* __restrict__ Wm, const float* __restrict__ bm,
    const float* __restrict__ Wlv, const float* __restrict__ blv,
    float* __restrict__ out)
{
    __shared__ float hn[512];
    int b = blockIdx.x, m = threadIdx.x;
    for (int i = m; i < 512; i += 128)
        hn[i] = (i < 256) ? g_H[i * 128 + b] : g_H[Dn * Bn + (i - 256) * 128 + b];
    __syncthreads();
    float am = bm[m], alv = blv[m];
    for (int k = 0; k < 512; k++) {
        float h = hn[k];
        am  += h * Wm [k * 128 + m];
        alv += h * Wlv[k * 128 + m];
    }
    out[b * 128 + m] = am;
    out[16384 + b * 128 + m] = sqrtf(expf(alv) + 1e-4f);
}

// ---------------- launch ----------------
extern "C" void kernel_launch(void* const* d_in, const int* in_sizes, int n_in,
                              void* d_out, int out_size) {
    const float* data = (const float*)d_in[0];
    const float* icWf = (const float*)d_in[1];
    const float* icUf = (const float*)d_in[2];
    const float* icbf = (const float*)d_in[3];
    const float* icWb = (const float*)d_in[4];
    const float* icUb = (const float*)d_in[5];
    const float* icbb = (const float*)d_in[6];
    const float* ich0 = (const float*)d_in[7];
    const float* ciWf = (const float*)d_in[8];
    const float* ciUf = (const float*)d_in[9];
    const float* cibf = (const float*)d_in[10];
    const float* ciWb = (const float*)d_in[11];
    const float* ciUb = (const float*)d_in[12];
    const float* cibb = (const float*)d_in[13];
    const float* cih0 = (const float*)d_in[14];
    const float* Wm   = (const float*)d_in[15];
    const float* bm   = (const float*)d_in[16];
    const float* Wlv  = (const float*)d_in[17];
    const float* blv  = (const float*)d_in[18];
    float* out = (float*)d_out;

    cudaFuncSetAttribute(scan_kernel, cudaFuncAttributeMaxDynamicSharedMemorySize,
                         SCAN_SMEM_BYTES);

    init_kernel<<<512, 256>>>(ich0, cih0, out);

    dim3 grid(24, 1024);
    xproj_kernel<<<grid, 256>>>(data, icWf, icWb, ciWf, ciWb,
                                icbf, icbb, cibf, cibb);

    scan_kernel<<<128, 256, SCAN_SMEM_BYTES>>>(icUf, icUb, ciUf, ciUb, out);

    head_kernel<<<128, 128>>>(Wm, bm, Wlv, blv, out);
}

// round 5
// speedup vs baseline: 1.9291x; 1.2113x over previous
#include <cuda_runtime.h>
#include <math.h>

#define Tn 1024
#define Bn 128
#define Nn 256
#define Dn 256

// ---------------- static device scratch ----------------
// NEW layout: g_XP[((t*4 + g)*768 + col)*128 + b]
__device__ float g_XP[(size_t)Bn * Tn * 3072];
__device__ float g_H [4 * Dn * Bn];              // [g][k][b]
__device__ float g_RH[4 * Dn * Bn];              // [g][k][b]
__device__ unsigned g_bar[4];

// ---------------- f32x2 helpers ----------------
static __device__ __forceinline__ unsigned long long pk2(float lo, float hi) {
    unsigned long long r;
    asm("mov.b64 %0, {%1, %2};" : "=l"(r) : "f"(lo), "f"(hi));
    return r;
}
static __device__ __forceinline__ void up2(unsigned long long v, float& lo, float& hi) {
    asm("mov.b64 {%0, %1}, %2;" : "=f"(lo), "=f"(hi) : "l"(v));
}
static __device__ __forceinline__ void fma2(unsigned long long& d,
                                            unsigned long long a,
                                            unsigned long long b) {
    asm("fma.rn.f32x2 %0, %1, %2, %0;" : "+l"(d) : "l"(a), "l"(b));
}
static __device__ __forceinline__ float sigf(float x) {
    return 1.0f / (1.0f + __expf(-x));
}
static __device__ __forceinline__ float tanhfast(float x) {
    float e = __expf(2.0f * x);
    return 1.0f - 2.0f / (e + 1.0f);
}

// ---------------- cp.async helpers ----------------
static __device__ __forceinline__ void cpa16(void* smem, const void* gmem) {
    unsigned s = (unsigned)__cvta_generic_to_shared(smem);
    asm volatile("cp.async.cg.shared.global [%0], [%1], 16;" :: "r"(s), "l"(gmem));
}
#define CPA_COMMIT() asm volatile("cp.async.commit_group;")
#define CPA_WAIT(n)  asm volatile("cp.async.wait_group %0;" :: "n"(n))

// ---------------- init ----------------
__global__ void init_kernel(const float* __restrict__ ic_h0,
                            const float* __restrict__ ci_h0,
                            float* __restrict__ out) {
    int i = blockIdx.x * 256 + threadIdx.x;
    if (i < 4 * Dn * Bn) {
        int g = i / (Dn * Bn);
        int k = (i % (Dn * Bn)) / Bn;
        const float* h0 = (g < 2) ? ic_h0 : ci_h0;
        g_H[i] = h0[(g & 1) * Dn + k];
    }
    if (i < Bn * Dn) {
        int b = i / Dn, d = i % Dn;
        float* ci = out + 32768;
        ci[((size_t)b * Tn) * 512 + d] = 0.0f;
        ci[((size_t)b * Tn + (Tn - 1)) * 512 + 256 + d] = 0.0f;
    }
    if (i < 4) g_bar[i] = 0u;
}

// ---------------- xproj SGEMM (f32x2, transposed output) ----------------
// Per CTA: fixed t (blockIdx.y), 128 b-rows x 128 cols (blockIdx.x of 24).
__global__ void __launch_bounds__(256) xproj_kernel(
    const float* __restrict__ X,
    const float* __restrict__ W0, const float* __restrict__ W1,
    const float* __restrict__ W2, const float* __restrict__ W3,
    const float* __restrict__ b0, const float* __restrict__ b1,
    const float* __restrict__ b2, const float* __restrict__ b3)
{
    __shared__ float As[8][128];
    __shared__ float Bs[8][128];

    const int t_  = blockIdx.y;
    const int n0  = blockIdx.x * 128;
    const int g   = n0 / 768;
    const int nc  = n0 - g * 768;
    const float* W    = (g == 0) ? W0 : (g == 1) ? W1 : (g == 2) ? W2 : W3;
    const float* bias = (g == 0) ? b0 : (g == 1) ? b1 : (g == 2) ? b2 : b3;

    const int tid  = threadIdx.x;
    const int warp = tid >> 5, lane = tid & 31;
    const int row0 = (warp & 3) * 32 + (lane >> 3) * 8;   // b
    const int col0 = (warp >> 2) * 64 + (lane & 7) * 8;

    const int am = tid >> 1, ak = (tid & 1) * 4;
    const int bk = tid >> 5, bn = (tid & 31) * 4;

    unsigned long long acc[8][4];
    #pragma unroll
    for (int i = 0; i < 8; i++)
        #pragma unroll
        for (int j = 0; j < 4; j++) acc[i][j] = 0ULL;

    for (int k0 = 0; k0 < 256; k0 += 8) {
        float4 av = __ldg((const float4*)&X[(size_t)am * (Tn * 256) + t_ * 256 + k0 + ak]);
        float4 bv = __ldg((const float4*)&W[(size_t)(k0 + bk) * 768 + nc + bn]);
        __syncthreads();
        As[ak + 0][am] = av.x; As[ak + 1][am] = av.y;
        As[ak + 2][am] = av.z; As[ak + 3][am] = av.w;
        *(float4*)&Bs[bk][bn] = bv;
        __syncthreads();

        #pragma unroll
        for (int kk = 0; kk < 8; ++kk) {
            float4 a0 = *(const float4*)&As[kk][row0];
            float4 a1 = *(const float4*)&As[kk][row0 + 4];
            ulonglong2 b01 = *(const ulonglong2*)&Bs[kk][col0];
            ulonglong2 b23 = *(const ulonglong2*)&Bs[kk][col0 + 4];
            float ar[8] = {a0.x, a0.y, a0.z, a0.w, a1.x, a1.y, a1.z, a1.w};
            #pragma unroll
            for (int i = 0; i < 8; i++) {
                unsigned long long ai = pk2(ar[i], ar[i]);
                fma2(acc[i][0], ai, b01.x);
                fma2(acc[i][1], ai, b01.y);
                fma2(acc[i][2], ai, b23.x);
                fma2(acc[i][3], ai, b23.y);
            }
        }
    }

    float c[8][8];
    #pragma unroll
    for (int i = 0; i < 8; i++) {
        up2(acc[i][0], c[i][0], c[i][1]);
        up2(acc[i][1], c[i][2], c[i][3]);
        up2(acc[i][2], c[i][4], c[i][5]);
        up2(acc[i][3], c[i][6], c[i][7]);
    }
    #pragma unroll
    for (int j = 0; j < 8; j++) {
        float bb = bias[nc + col0 + j];
        size_t base = ((size_t)(t_ * 4 + g) * 768 + nc + col0 + j) * 128 + row0;
        float4 v0 = make_float4(c[0][j] + bb, c[1][j] + bb, c[2][j] + bb, c[3][j] + bb);
        float4 v1 = make_float4(c[4][j] + bb, c[5][j] + bb, c[6][j] + bb, c[7][j] + bb);
        __stcg((float4*)&g_XP[base],     v0);
        __stcg((float4*)&g_XP[base + 4], v1);
    }
}

// ---------------- per-GRU grid barrier ----------------
static __device__ __forceinline__ void gbar(int g, unsigned target) {
    __syncthreads();
    if (threadIdx.x == 0) {
        __threadfence();
        atomicAdd(&g_bar[g], 1u);
        while (*((volatile unsigned*)&g_bar[g]) < target) { __nanosleep(32); }
        __threadfence();
    }
    __syncthreads();
}

// ---------------- scan smem layout (floats) ----------------
#define HS_OFF   0                       // 32768 : H / RH tile [256][128]
#define U1_OFF   32768                   // 4096  : zr U slab [256][16]
#define U2_OFF   (U1_OFF + 4096)         // 2048  : hh U slab [256][8]
#define XP_OFF   (U2_OFF + 2048)         // 6144  : XP double buffer [2][24][128]
#define ZS_OFF   (XP_OFF + 6144)         // 1024  : z gate [8][128]
#define HSV_OFF  (ZS_OFF + 1024)         // 1024  : saved old-H rows [8][128]
#define SCAN_SMEM_FLOATS (HSV_OFF + 1024)
#define SCAN_SMEM_BYTES  (SCAN_SMEM_FLOATS * 4)   // 188416 B

// ---------------- persistent scan: 128 CTAs = 4 GRUs x 32 ----------------
__global__ void __launch_bounds__(256, 1) scan_kernel(
    const float* __restrict__ U0, const float* __restrict__ U1,
    const float* __restrict__ U2, const float* __restrict__ U3,
    float* __restrict__ out)
{
    extern __shared__ float sm[];
    float* Hs   = sm + HS_OFF;
    float* U1s  = sm + U1_OFF;
    float* U2s  = sm + U2_OFF;
    float* XPd  = sm + XP_OFF;
    float* Zs   = sm + ZS_OFF;
    float* HsSv = sm + HSV_OFF;

    const int g   = blockIdx.x >> 5;
    const int c   = blockIdx.x & 31;
    const int c8  = c * 8;
    const int tid = threadIdx.x;
    const float* U = (g == 0) ? U0 : (g == 1) ? U1 : (g == 2) ? U2 : U3;

    // resident U slabs
    for (int i = tid; i < Dn * 16; i += 256) {
        int k = i >> 4, jj = i & 15;
        int col = (jj < 8) ? (c8 + jj) : (256 + c8 + (jj - 8));
        U1s[i] = U[k * 768 + col];
    }
    for (int i = tid; i < Dn * 8; i += 256) {
        int k = i >> 3, jj = i & 7;
        U2s[i] = U[k * 768 + 512 + c8 + jj];
    }

    // thread tiles (FMA on warps 0-3 only, one per SMSP)
    const int q    = (tid >> 6) & 1;       // group within the 128 active threads
    const int j0p1 = q * 8;                // phase1: 8 j-cols (q=0: z, q=1: r)
    const int j0p2 = q * 4;                // phase2: 4 j-cols
    const int b    = (tid & 63) * 2;

    float* myH  = g_H  + g * Dn * Bn;
    float* myRH = g_RH + g * Dn * Bn;
    float* ci   = out + 32768;
    unsigned tgt = 0;

    // preload XP(0) into buffer 0
    {
        int t0 = (g & 1) ? (Tn - 1) : 0;
        const float* xpb = g_XP + ((size_t)t0 * 4 + g) * 98304;
        #pragma unroll
        for (int i = 0; i < 3; i++) {
            int f = i * 256 + tid;
            int jj = f >> 5, w = f & 31;
            int col = (jj < 8) ? (c8 + jj) : (jj < 16) ? (256 + c8 + jj - 8)
                                           : (512 + c8 + jj - 16);
            cpa16(XPd + f * 4, xpb + col * 128 + w * 4);
        }
        CPA_COMMIT();
        CPA_WAIT(0);
    }
    __syncthreads();

    for (int s = 0; s < Tn; s++) {
        const float* XPc = XPd + (s & 1) * 3072;

        // ---- issue H chunks (4 groups) + XP prefetch for s+1 (1 group) ----
        #pragma unroll
        for (int ch = 0; ch < 4; ch++) {
            int f0 = ch * 2048 + tid;
            #pragma unroll
            for (int r = 0; r < 8; r++)
                cpa16(Hs + (f0 + r * 256) * 4, myH + (f0 + r * 256) * 4);
            CPA_COMMIT();
        }
        {
            int sn = (s < Tn - 1) ? (s + 1) : s;
            int tn_ = (g & 1) ? (Tn - 1 - sn) : sn;
            const float* xpb = g_XP + ((size_t)tn_ * 4 + g) * 98304;
            float* dst = XPd + ((s + 1) & 1) * 3072;
            #pragma unroll
            for (int i = 0; i < 3; i++) {
                int f = i * 256 + tid;
                int jj = f >> 5, w = f & 31;
                int col = (jj < 8) ? (c8 + jj) : (jj < 16) ? (256 + c8 + jj - 8)
                                               : (512 + c8 + jj - 16);
                cpa16(dst + f * 4, xpb + col * 128 + w * 4);
            }
            CPA_COMMIT();
        }

        // ---- phase 1: zr pre-activation (4 warps, 4jp x 2b) ----
        unsigned long long acc[4][2];
        if (tid < 128) {
            #pragma unroll
            for (int jp = 0; jp < 4; jp++) {
                int j = j0p1 + 2 * jp;
                acc[jp][0] = pk2(XPc[j * 128 + b],     XPc[(j + 1) * 128 + b]);
                acc[jp][1] = pk2(XPc[j * 128 + b + 1], XPc[(j + 1) * 128 + b + 1]);
            }
        }
        #pragma unroll
        for (int ch = 0; ch < 4; ch++) {
            if (ch == 0)      { CPA_WAIT(4); }
            else if (ch == 1) { CPA_WAIT(3); }
            else if (ch == 2) { CPA_WAIT(2); }
            else              { CPA_WAIT(1); }
            __syncthreads();
            if (tid < 128) {
                #pragma unroll 4
                for (int k = ch * 64; k < ch * 64 + 64; k++) {
                    ulonglong2 ua = *(const ulonglong2*)(U1s + k * 16 + j0p1);
                    ulonglong2 ub = *(const ulonglong2*)(U1s + k * 16 + j0p1 + 4);
                    float2 h2 = *(const float2*)(Hs + k * 128 + b);
                    unsigned long long h0 = pk2(h2.x, h2.x);
                    unsigned long long h1 = pk2(h2.y, h2.y);
                    fma2(acc[0][0], ua.x, h0); fma2(acc[0][1], ua.x, h1);
                    fma2(acc[1][0], ua.y, h0); fma2(acc[1][1], ua.y, h1);
                    fma2(acc[2][0], ub.x, h0); fma2(acc[2][1], ub.x, h1);
                    fma2(acc[3][0], ub.y, h0); fma2(acc[3][1], ub.y, h1);
                }
            }
        }
        if (tid < 128) {
            if (q == 0) {       // z cols 0..7 -> Zs
                #pragma unroll
                for (int jp = 0; jp < 4; jp++) {
                    float v00, v10, v01, v11;
                    up2(acc[jp][0], v00, v10);
                    up2(acc[jp][1], v01, v11);
                    int j = 2 * jp;
                    *(float2*)(Zs + j * 128 + b)       = make_float2(sigf(v00), sigf(v01));
                    *(float2*)(Zs + (j + 1) * 128 + b) = make_float2(sigf(v10), sigf(v11));
                }
            } else {            // r cols -> r*h -> global RH
                #pragma unroll
                for (int jp = 0; jp < 4; jp++) {
                    float v00, v10, v01, v11;
                    up2(acc[jp][0], v00, v10);
                    up2(acc[jp][1], v01, v11);
                    int d = c8 + 2 * jp;
                    float2 ha = *(const float2*)(Hs + d * 128 + b);
                    float2 hb = *(const float2*)(Hs + (d + 1) * 128 + b);
                    __stcg((float2*)(myRH + d * 128 + b),
                           make_float2(sigf(v00) * ha.x, sigf(v01) * ha.y));
                    __stcg((float2*)(myRH + (d + 1) * 128 + b),
                           make_float2(sigf(v10) * hb.x, sigf(v11) * hb.y));
                }
            }
        }
        // save old-H rows this CTA will need for the update
        for (int i = tid; i < 1024; i += 256)
            HsSv[i] = Hs[(c8 + (i >> 7)) * 128 + (i & 127)];

        tgt += 32;
        gbar(g, tgt);

        // ---- issue RH chunks ----
        #pragma unroll
        for (int ch = 0; ch < 4; ch++) {
            int f0 = ch * 2048 + tid;
            #pragma unroll
            for (int r = 0; r < 8; r++)
                cpa16(Hs + (f0 + r * 256) * 4, myRH + (f0 + r * 256) * 4);
            CPA_COMMIT();
        }

        // ---- phase 2: candidate + update (4 warps, 2jp x 2b) ----
        unsigned long long acc2[2][2];
        if (tid < 128) {
            #pragma unroll
            for (int jp = 0; jp < 2; jp++) {
                int j = j0p2 + 2 * jp;
                acc2[jp][0] = pk2(XPc[(16 + j) * 128 + b],     XPc[(16 + j + 1) * 128 + b]);
                acc2[jp][1] = pk2(XPc[(16 + j) * 128 + b + 1], XPc[(16 + j + 1) * 128 + b + 1]);
            }
        }
        #pragma unroll
        for (int ch = 0; ch < 4; ch++) {
            if (ch == 0)      { CPA_WAIT(3); }
            else if (ch == 1) { CPA_WAIT(2); }
            else if (ch == 2) { CPA_WAIT(1); }
            else              { CPA_WAIT(0); }
            __syncthreads();
            if (tid < 128) {
                #pragma unroll 4
                for (int k = ch * 64; k < ch * 64 + 64; k++) {
                    ulonglong2 u = *(const ulonglong2*)(U2s + k * 8 + j0p2);
                    float2 h2 = *(const float2*)(Hs + k * 128 + b);
                    unsigned long long h0 = pk2(h2.x, h2.x);
                    unsigned long long h1 = pk2(h2.y, h2.y);
                    fma2(acc2[0][0], u.x, h0); fma2(acc2[0][1], u.x, h1);
                    fma2(acc2[1][0], u.y, h0); fma2(acc2[1][1], u.y, h1);
                }
            }
        }
        if (tid < 128) {
            float hn[4][2];
            #pragma unroll
            for (int jp = 0; jp < 2; jp++) {
                float v00, v10, v01, v11;
                up2(acc2[jp][0], v00, v10);
                up2(acc2[jp][1], v01, v11);
                float xv[2][2] = {{v00, v01}, {v10, v11}};
                #pragma unroll
                for (int l = 0; l < 2; l++) {
                    int jl = j0p2 + 2 * jp + l;
                    #pragma unroll
                    for (int bb_ = 0; bb_ < 2; bb_++) {
                        float cand = tanhfast(xv[l][bb_]);
                        float z  = Zs[jl * 128 + b + bb_];
                        float ho = HsSv[jl * 128 + b + bb_];
                        float v  = z * ho + (1.0f - z) * cand;
                        hn[2 * jp + l][bb_] = fminf(5.0f, fmaxf(-5.0f, v));
                    }
                }
            }
            #pragma unroll
            for (int qq = 0; qq < 4; qq++) {
                int d = c8 + j0p2 + qq;
                __stcg((float2*)(myH + d * 128 + b),
                       make_float2(hn[qq][0], hn[qq][1]));
            }
            if (g >= 2 && s < Tn - 1) {
                int d0 = c8 + j0p2;
                #pragma unroll
                for (int bb_ = 0; bb_ < 2; bb_++) {
                    float4 q4 = make_float4(hn[0][bb_], hn[1][bb_],
                                            hn[2][bb_], hn[3][bb_]);
                    size_t row = (g == 2)
                        ? ((size_t)(b + bb_) * Tn + s + 1) * 512 + d0
                        : ((size_t)(b + bb_) * Tn + (Tn - 2 - s)) * 512 + 256 + d0;
                    __stcg((float4*)(ci + row), q4);
                }
            }
        }
        tgt += 32;
        gbar(g, tgt);
    }
}

// ---------------- heads ----------------
__global__ void __launch_bounds__(128) head_kernel(
    const float* __restrict__ Wm, const float* __restrict__ bm,
    const float* __restrict__ Wlv, const float* __restrict__ blv,
    float* __restrict__ out)
{
    __shared__ float hn[512];
    int b = blockIdx.x, m = threadIdx.x;
    for (int i = m; i < 512; i += 128)
        hn[i] = (i < 256) ? g_H[i * 128 + b] : g_H[Dn * Bn + (i - 256) * 128 + b];
    __syncthreads();
    float am = bm[m], alv = blv[m];
    for (int k = 0; k < 512; k++) {
        float h = hn[k];
        am  += h * Wm [k * 128 + m];
        alv += h * Wlv[k * 128 + m];
    }
    out[b * 128 + m] = am;
    out[16384 + b * 128 + m] = sqrtf(expf(alv) + 1e-4f);
}

// ---------------- launch ----------------
extern "C" void kernel_launch(void* const* d_in, const int* in_sizes, int n_in,
                              void* d_out, int out_size) {
    const float* data = (const float*)d_in[0];
    const float* icWf = (const float*)d_in[1];
    const float* icUf = (const float*)d_in[2];
    const float* icbf = (const float*)d_in[3];
    const float* icWb = (const float*)d_in[4];
    const float* icUb = (const float*)d_in[5];
    const float* icbb = (const float*)d_in[6];
    const float* ich0 = (const float*)d_in[7];
    const float* ciWf = (const float*)d_in[8];
    const float* ciUf = (const float*)d_in[9];
    const float* cibf = (const float*)d_in[10];
    const float* ciWb = (const float*)d_in[11];
    const float* ciUb = (const float*)d_in[12];
    const float* cibb = (const float*)d_in[13];
    const float* cih0 = (const float*)d_in[14];
    const float* Wm   = (const float*)d_in[15];
    const float* bm   = (const float*)d_in[16];
    const float* Wlv  = (const float*)d_in[17];
    const float* blv  = (const float*)d_in[18];
    float* out = (float*)d_out;

    cudaFuncSetAttribute(scan_kernel, cudaFuncAttributeMaxDynamicSharedMemorySize,
                         SCAN_SMEM_BYTES);

    init_kernel<<<512, 256>>>(ich0, cih0, out);

    dim3 grid(24, Tn);
    xproj_kernel<<<grid, 256>>>(data, icWf, icWb, ciWf, ciWb,
                                icbf, icbb, cibf, cibb);

    scan_kernel<<<128, 256, SCAN_SMEM_BYTES>>>(icUf, icUb, ciUf, ciUb, out);

    head_kernel<<<128, 128>>>(Wm, bm, Wlv, blv, out);
}

// round 6
// speedup vs baseline: 1.9909x; 1.0320x over previous
#include <cuda_runtime.h>
#include <math.h>

#define Tn 1024
#define Bn 128
#define Nn 256
#define Dn 256

// ---------------- static device scratch ----------------
// g_XP[((t*4 + g)*768 + col)*128 + b]
__device__ float g_XP[(size_t)Bn * Tn * 3072];
// g_H / g_RH: [(g*4 + pgroup)*256 + k]*32 + b32   (batch-group-sliced)
__device__ float g_H [16 * 256 * 32];
__device__ float g_RH[16 * 256 * 32];
__device__ unsigned g_bar[16];

// ---------------- f32x2 helpers ----------------
static __device__ __forceinline__ unsigned long long pk2(float lo, float hi) {
    unsigned long long r;
    asm("mov.b64 %0, {%1, %2};" : "=l"(r) : "f"(lo), "f"(hi));
    return r;
}
static __device__ __forceinline__ void up2(unsigned long long v, float& lo, float& hi) {
    asm("mov.b64 {%0, %1}, %2;" : "=f"(lo), "=f"(hi) : "l"(v));
}
static __device__ __forceinline__ void fma2(unsigned long long& d,
                                            unsigned long long a,
                                            unsigned long long b) {
    asm("fma.rn.f32x2 %0, %1, %2, %0;" : "+l"(d) : "l"(a), "l"(b));
}
static __device__ __forceinline__ float sigf(float x) {
    return 1.0f / (1.0f + __expf(-x));
}
static __device__ __forceinline__ float tanhfast(float x) {
    float e = __expf(2.0f * x);
    return 1.0f - 2.0f / (e + 1.0f);
}

// ---------------- cp.async helpers ----------------
static __device__ __forceinline__ void cpa16(void* smem, const void* gmem) {
    unsigned s = (unsigned)__cvta_generic_to_shared(smem);
    asm volatile("cp.async.cg.shared.global [%0], [%1], 16;" :: "r"(s), "l"(gmem));
}
#define CPA_COMMIT() asm volatile("cp.async.commit_group;")
#define CPA_WAIT(n)  asm volatile("cp.async.wait_group %0;" :: "n"(n))

// ---------------- init ----------------
__global__ void init_kernel(const float* __restrict__ ic_h0,
                            const float* __restrict__ ci_h0,
                            float* __restrict__ out) {
    int i = blockIdx.x * 256 + threadIdx.x;
    if (i < 16 * 256 * 32) {
        int gi = i >> 13;          // (g*4+p)
        int g  = gi >> 2;
        int k  = (i >> 5) & 255;
        const float* h0 = (g < 2) ? ic_h0 : ci_h0;
        g_H[i] = h0[(g & 1) * Dn + k];
    }
    if (i < Bn * Dn) {
        int b = i / Dn, d = i % Dn;
        float* ci = out + 32768;
        ci[((size_t)b * Tn) * 512 + d] = 0.0f;
        ci[((size_t)b * Tn + (Tn - 1)) * 512 + 256 + d] = 0.0f;
    }
    if (i < 16) g_bar[i] = 0u;
}

// ---------------- xproj SGEMM (f32x2, transposed output) ----------------
__global__ void __launch_bounds__(256) xproj_kernel(
    const float* __restrict__ X,
    const float* __restrict__ W0, const float* __restrict__ W1,
    const float* __restrict__ W2, const float* __restrict__ W3,
    const float* __restrict__ b0, const float* __restrict__ b1,
    const float* __restrict__ b2, const float* __restrict__ b3)
{
    __shared__ float As[8][128];
    __shared__ float Bs[8][128];

    const int t_  = blockIdx.y;
    const int n0  = blockIdx.x * 128;
    const int g   = n0 / 768;
    const int nc  = n0 - g * 768;
    const float* W    = (g == 0) ? W0 : (g == 1) ? W1 : (g == 2) ? W2 : W3;
    const float* bias = (g == 0) ? b0 : (g == 1) ? b1 : (g == 2) ? b2 : b3;

    const int tid  = threadIdx.x;
    const int warp = tid >> 5, lane = tid & 31;
    const int row0 = (warp & 3) * 32 + (lane >> 3) * 8;   // b
    const int col0 = (warp >> 2) * 64 + (lane & 7) * 8;

    const int am = tid >> 1, ak = (tid & 1) * 4;
    const int bk = tid >> 5, bn = (tid & 31) * 4;

    unsigned long long acc[8][4];
    #pragma unroll
    for (int i = 0; i < 8; i++)
        #pragma unroll
        for (int j = 0; j < 4; j++) acc[i][j] = 0ULL;

    for (int k0 = 0; k0 < 256; k0 += 8) {
        float4 av = __ldg((const float4*)&X[(size_t)am * (Tn * 256) + t_ * 256 + k0 + ak]);
        float4 bv = __ldg((const float4*)&W[(size_t)(k0 + bk) * 768 + nc + bn]);
        __syncthreads();
        As[ak + 0][am] = av.x; As[ak + 1][am] = av.y;
        As[ak + 2][am] = av.z; As[ak + 3][am] = av.w;
        *(float4*)&Bs[bk][bn] = bv;
        __syncthreads();

        #pragma unroll
        for (int kk = 0; kk < 8; ++kk) {
            float4 a0 = *(const float4*)&As[kk][row0];
            float4 a1 = *(const float4*)&As[kk][row0 + 4];
            ulonglong2 b01 = *(const ulonglong2*)&Bs[kk][col0];
            ulonglong2 b23 = *(const ulonglong2*)&Bs[kk][col0 + 4];
            float ar[8] = {a0.x, a0.y, a0.z, a0.w, a1.x, a1.y, a1.z, a1.w};
            #pragma unroll
            for (int i = 0; i < 8; i++) {
                unsigned long long ai = pk2(ar[i], ar[i]);
                fma2(acc[i][0], ai, b01.x);
                fma2(acc[i][1], ai, b01.y);
                fma2(acc[i][2], ai, b23.x);
                fma2(acc[i][3], ai, b23.y);
            }
        }
    }

    float c[8][8];
    #pragma unroll
    for (int i = 0; i < 8; i++) {
        up2(acc[i][0], c[i][0], c[i][1]);
        up2(acc[i][1], c[i][2], c[i][3]);
        up2(acc[i][2], c[i][4], c[i][5]);
        up2(acc[i][3], c[i][6], c[i][7]);
    }
    #pragma unroll
    for (int j = 0; j < 8; j++) {
        float bb = bias[nc + col0 + j];
        size_t base = ((size_t)(t_ * 4 + g) * 768 + nc + col0 + j) * 128 + row0;
        float4 v0 = make_float4(c[0][j] + bb, c[1][j] + bb, c[2][j] + bb, c[3][j] + bb);
        float4 v1 = make_float4(c[4][j] + bb, c[5][j] + bb, c[6][j] + bb, c[7][j] + bb);
        __stcg((float4*)&g_XP[base],     v0);
        __stcg((float4*)&g_XP[base + 4], v1);
    }
}

// ---------------- per-group grid barrier (8 CTAs) ----------------
static __device__ __forceinline__ void gbar(int gi, unsigned target) {
    __syncthreads();
    if (threadIdx.x == 0) {
        __threadfence();
        atomicAdd(&g_bar[gi], 1u);
        while (*((volatile unsigned*)&g_bar[gi]) < target) { __nanosleep(32); }
        __threadfence();
    }
    __syncthreads();
}

// ---------------- scan smem layout (floats) ----------------
#define HS_OFF   0                        // 8192  : H/RH batch-slice [256][32]
#define U1_OFF   8192                     // 16384 : zr U slab [256][64]
#define U2_OFF   (U1_OFF + 16384)         // 8192  : hh U slab [256][32]
#define XP_OFF   (U2_OFF + 8192)          // 6144  : XP double buffer [2][96][32]
#define ZS_OFF   (XP_OFF + 6144)          // 1024  : z gate [32][32]
#define HSV_OFF  (ZS_OFF + 1024)          // 1024  : saved old-H [32][32]
#define SCAN_SMEM_FLOATS (HSV_OFF + 1024)
#define SCAN_SMEM_BYTES  (SCAN_SMEM_FLOATS * 4)   // 163840 B

// ---------------- persistent scan: 128 CTAs = 4 GRU x 4 bgroup x 8 colslice ----------------
__global__ void __launch_bounds__(256, 1) scan_kernel(
    const float* __restrict__ U0, const float* __restrict__ U1,
    const float* __restrict__ U2, const float* __restrict__ U3,
    float* __restrict__ out)
{
    extern __shared__ float sm[];
    float* Hs   = sm + HS_OFF;
    float* U1s  = sm + U1_OFF;
    float* U2s  = sm + U2_OFF;
    float* XPd  = sm + XP_OFF;
    float* Zs   = sm + ZS_OFF;
    float* HsSv = sm + HSV_OFF;

    const int g   = blockIdx.x >> 5;
    const int pg  = (blockIdx.x >> 3) & 3;   // batch group
    const int cs  = blockIdx.x & 7;          // column slice
    const int d0  = cs * 32;
    const int gi  = g * 4 + pg;
    const int tid = threadIdx.x;
    const int b   = tid & 31;
    const int jo  = tid >> 5;                // 0..7
    const float* U = (g == 0) ? U0 : (g == 1) ? U1 : (g == 2) ? U2 : U3;

    // resident U slabs
    for (int i = tid; i < 256 * 64; i += 256) {
        int k = i >> 6, jj = i & 63;
        int col = (jj < 32) ? (d0 + jj) : (256 + d0 + jj - 32);
        U1s[i] = U[k * 768 + col];
    }
    for (int i = tid; i < 256 * 32; i += 256) {
        int k = i >> 5, jj = i & 31;
        U2s[i] = U[k * 768 + 512 + d0 + jj];
    }

    float* myH  = g_H  + gi * 8192;
    float* myRH = g_RH + gi * 8192;
    float* ci   = out + 32768;
    unsigned tgt = 0;

    const int j1 = jo * 8;     // phase1: 8 zr cols of 64
    const int j2 = jo * 4;     // phase2: 4 hh cols of 32

    // ---- prologue: stage H + XP(0) ----
    #pragma unroll
    for (int ch = 0; ch < 2; ch++) {
        #pragma unroll
        for (int r = 0; r < 4; r++)
            cpa16(Hs + ch * 4096 + (r * 256 + tid) * 4,
                  myH + ch * 4096 + (r * 256 + tid) * 4);
        CPA_COMMIT();
    }
    {
        int t0 = (g & 1) ? (Tn - 1) : 0;
        const float* xpb = g_XP + ((size_t)t0 * 4 + g) * 98304;
        #pragma unroll
        for (int i = 0; i < 3; i++) {
            int idx = i * 256 + tid;
            int cl = idx >> 3, seg = idx & 7;
            int gcol = (cl < 32) ? (d0 + cl) : (cl < 64) ? (256 + d0 + cl - 32)
                                             : (512 + d0 + cl - 64);
            cpa16(XPd + cl * 32 + seg * 4, xpb + gcol * 128 + pg * 32 + seg * 4);
        }
        CPA_COMMIT();
    }
    CPA_WAIT(0);
    __syncthreads();

    for (int s = 0; s < Tn; s++) {
        const float* XPc = XPd + (s & 1) * 3072;

        // ---- prefetch XP(s+1) ----
        {
            int sn = (s < Tn - 1) ? (s + 1) : s;
            int tn_ = (g & 1) ? (Tn - 1 - sn) : sn;
            const float* xpb = g_XP + ((size_t)tn_ * 4 + g) * 98304;
            float* dst = XPd + ((s + 1) & 1) * 3072;
            #pragma unroll
            for (int i = 0; i < 3; i++) {
                int idx = i * 256 + tid;
                int cl = idx >> 3, seg = idx & 7;
                int gcol = (cl < 32) ? (d0 + cl) : (cl < 64) ? (256 + d0 + cl - 32)
                                                 : (512 + d0 + cl - 64);
                cpa16(dst + cl * 32 + seg * 4, xpb + gcol * 128 + pg * 32 + seg * 4);
            }
            CPA_COMMIT();
        }

        // ---- phase 1: zr pre-activation (H fully resident) ----
        unsigned long long acc[4];
        #pragma unroll
        for (int p = 0; p < 4; p++)
            acc[p] = pk2(XPc[(j1 + 2 * p) * 32 + b], XPc[(j1 + 2 * p + 1) * 32 + b]);

        // H chunk waits interleave with compute (outstanding: [H0,H1,XP] at s>0)
        CPA_WAIT(2);
        __syncthreads();
        #pragma unroll 4
        for (int k = 0; k < 128; k++) {
            ulonglong2 ua = *(const ulonglong2*)(U1s + k * 64 + j1);
            ulonglong2 ub = *(const ulonglong2*)(U1s + k * 64 + j1 + 4);
            float h = Hs[k * 32 + b];
            unsigned long long hd = pk2(h, h);
            fma2(acc[0], ua.x, hd); fma2(acc[1], ua.y, hd);
            fma2(acc[2], ub.x, hd); fma2(acc[3], ub.y, hd);
        }
        CPA_WAIT(1);
        __syncthreads();
        #pragma unroll 4
        for (int k = 128; k < 256; k++) {
            ulonglong2 ua = *(const ulonglong2*)(U1s + k * 64 + j1);
            ulonglong2 ub = *(const ulonglong2*)(U1s + k * 64 + j1 + 4);
            float h = Hs[k * 32 + b];
            unsigned long long hd = pk2(h, h);
            fma2(acc[0], ua.x, hd); fma2(acc[1], ua.y, hd);
            fma2(acc[2], ub.x, hd); fma2(acc[3], ub.y, hd);
        }

        // epilogue
        {
            float v[8];
            #pragma unroll
            for (int p = 0; p < 4; p++) up2(acc[p], v[2 * p], v[2 * p + 1]);
            if (jo < 4) {           // z cols (local 0..31)
                #pragma unroll
                for (int j = 0; j < 8; j++)
                    Zs[(j1 + j) * 32 + b] = sigf(v[j]);
            } else {                // r cols -> r*h -> gmem
                int jb = j1 - 32;
                #pragma unroll
                for (int j = 0; j < 8; j++) {
                    int d = d0 + jb + j;
                    float rh = sigf(v[j]) * Hs[d * 32 + b];
                    __stcg(myRH + d * 32 + b, rh);
                }
            }
            // save old-H for own cols (contiguous block)
            float4 hv = *(const float4*)(Hs + d0 * 32 + tid * 4);
            *(float4*)(HsSv + tid * 4) = hv;
        }
        __threadfence();
        tgt += 8;
        gbar(gi, tgt);

        // ---- stage RH (2 chunks) ----
        #pragma unroll
        for (int ch = 0; ch < 2; ch++) {
            #pragma unroll
            for (int r = 0; r < 4; r++)
                cpa16(Hs + ch * 4096 + (r * 256 + tid) * 4,
                      myRH + ch * 4096 + (r * 256 + tid) * 4);
            CPA_COMMIT();
        }

        // ---- phase 2: candidate + update ----
        unsigned long long acc2[2];
        #pragma unroll
        for (int p = 0; p < 2; p++)
            acc2[p] = pk2(XPc[(64 + j2 + 2 * p) * 32 + b],
                          XPc[(64 + j2 + 2 * p + 1) * 32 + b]);

        CPA_WAIT(1);
        __syncthreads();
        #pragma unroll 4
        for (int k = 0; k < 128; k++) {
            ulonglong2 u = *(const ulonglong2*)(U2s + k * 32 + j2);
            float h = Hs[k * 32 + b];
            unsigned long long hd = pk2(h, h);
            fma2(acc2[0], u.x, hd); fma2(acc2[1], u.y, hd);
        }
        CPA_WAIT(0);
        __syncthreads();
        #pragma unroll 4
        for (int k = 128; k < 256; k++) {
            ulonglong2 u = *(const ulonglong2*)(U2s + k * 32 + j2);
            float h = Hs[k * 32 + b];
            unsigned long long hd = pk2(h, h);
            fma2(acc2[0], u.x, hd); fma2(acc2[1], u.y, hd);
        }

        // epilogue: gate combine, clip, write H, ci
        {
            float w[4];
            up2(acc2[0], w[0], w[1]);
            up2(acc2[1], w[2], w[3]);
            float hn[4];
            #pragma unroll
            for (int j = 0; j < 4; j++) {
                int jl = j2 + j;
                float z  = Zs[jl * 32 + b];
                float ho = HsSv[jl * 32 + b];
                float cand = tanhfast(w[j]);
                float v = z * ho + (1.0f - z) * cand;
                hn[j] = fminf(5.0f, fmaxf(-5.0f, v));
                __stcg(myH + (d0 + jl) * 32 + b, hn[j]);
            }
            if (g >= 2 && s < Tn - 1) {
                int Bg = pg * 32 + b;
                size_t row = (g == 2)
                    ? ((size_t)Bg * Tn + s + 1) * 512 + d0 + j2
                    : ((size_t)Bg * Tn + (Tn - 2 - s)) * 512 + 256 + d0 + j2;
                __stcg((float4*)(ci + row), make_float4(hn[0], hn[1], hn[2], hn[3]));
            }
        }
        __threadfence();
        tgt += 8;
        gbar(gi, tgt);

        // ---- stage H for next step (overlaps loop turnaround) ----
        #pragma unroll
        for (int ch = 0; ch < 2; ch++) {
            #pragma unroll
            for (int r = 0; r < 4; r++)
                cpa16(Hs + ch * 4096 + (r * 256 + tid) * 4,
                      myH + ch * 4096 + (r * 256 + tid) * 4);
            CPA_COMMIT();
        }
    }
}

// ---------------- heads ----------------
__global__ void __launch_bounds__(128) head_kernel(
    const float* __restrict__ Wm, const float* __restrict__ bm,
    const float* __restrict__ Wlv, const float* __restrict__ blv,
    float* __restrict__ out)
{
    __shared__ float hn[512];
    int b = blockIdx.x, m = threadIdx.x;
    int pgr = b >> 5, b32 = b & 31;
    for (int i = m; i < 512; i += 128)
        hn[i] = (i < 256) ? g_H[((0 + pgr) * 256 + i) * 32 + b32]
                          : g_H[((4 + pgr) * 256 + (i - 256)) * 32 + b32];
    __syncthreads();
    float am = bm[m], alv = blv[m];
    for (int k = 0; k < 512; k++) {
        float h = hn[k];
        am  += h * Wm [k * 128 + m];
        alv += h * Wlv[k * 128 + m];
    }
    out[b * 128 + m] = am;
    out[16384 + b * 128 + m] = sqrtf(expf(alv) + 1e-4f);
}

// ---------------- launch ----------------
extern "C" void kernel_launch(void* const* d_in, const int* in_sizes, int n_in,
                              void* d_out, int out_size) {
    const float* data = (const float*)d_in[0];
    const float* icWf = (const float*)d_in[1];
    const float* icUf = (const float*)d_in[2];
    const float* icbf = (const float*)d_in[3];
    const float* icWb = (const float*)d_in[4];
    const float* icUb = (const float*)d_in[5];
    const float* icbb = (const float*)d_in[6];
    const float* ich0 = (const float*)d_in[7];
    const float* ciWf = (const float*)d_in[8];
    const float* ciUf = (const float*)d_in[9];
    const float* cibf = (const float*)d_in[10];
    const float* ciWb = (const float*)d_in[11];
    const float* ciUb = (const float*)d_in[12];
    const float* cibb = (const float*)d_in[13];
    const float* cih0 = (const float*)d_in[14];
    const float* Wm   = (const float*)d_in[15];
    const float* bm   = (const float*)d_in[16];
    const float* Wlv  = (const float*)d_in[17];
    const float* blv  = (const float*)d_in[18];
    float* out = (float*)d_out;

    cudaFuncSetAttribute(scan_kernel, cudaFuncAttributeMaxDynamicSharedMemorySize,
                         SCAN_SMEM_BYTES);

    init_kernel<<<512, 256>>>(ich0, cih0, out);

    dim3 grid(24, Tn);
    xproj_kernel<<<grid, 256>>>(data, icWf, icWb, ciWf, ciWb,
                                icbf, icbb, cibf, cibb);

    scan_kernel<<<128, 256, SCAN_SMEM_BYTES>>>(icUf, icUb, ciUf, ciUb, out);

    head_kernel<<<128, 128>>>(Wm, bm, Wlv, blv, out);
}

// round 8
// speedup vs baseline: 2.0807x; 1.0451x over previous
#include <cuda_runtime.h>
#include <math.h>

#define Tn 1024
#define Bn 128
#define Nn 256
#define Dn 256

// ---------------- static device scratch ----------------
// g_XP[((t*4 + g)*768 + col)*128 + b]
__device__ float g_XP[(size_t)Bn * Tn * 3072];
// g_H / g_RH: [(g*4 + pgroup)*256 + k]*32 + b32   (batch-group-sliced)
__device__ float g_H [16 * 256 * 32];
__device__ float g_RH[16 * 256 * 32];
__device__ unsigned g_bar[17];     // [0..15]: scan groups, [16]: head barrier

// ---------------- f32x2 helpers ----------------
static __device__ __forceinline__ unsigned long long pk2(float lo, float hi) {
    unsigned long long r;
    asm("mov.b64 %0, {%1, %2};" : "=l"(r) : "f"(lo), "f"(hi));
    return r;
}
static __device__ __forceinline__ void up2(unsigned long long v, float& lo, float& hi) {
    asm("mov.b64 {%0, %1}, %2;" : "=f"(lo), "=f"(hi) : "l"(v));
}
static __device__ __forceinline__ void fma2(unsigned long long& d,
                                            unsigned long long a,
                                            unsigned long long b) {
    asm("fma.rn.f32x2 %0, %1, %2, %0;" : "+l"(d) : "l"(a), "l"(b));
}
static __device__ __forceinline__ float sigf(float x) {
    return 1.0f / (1.0f + __expf(-x));
}
static __device__ __forceinline__ float tanhfast(float x) {
    float e = __expf(2.0f * x);
    return 1.0f - 2.0f / (e + 1.0f);
}

// ---------------- cp.async helpers ----------------
static __device__ __forceinline__ void cpa16(void* smem, const void* gmem) {
    unsigned s = (unsigned)__cvta_generic_to_shared(smem);
    asm volatile("cp.async.cg.shared.global [%0], [%1], 16;" :: "r"(s), "l"(gmem));
}
#define CPA_COMMIT() asm volatile("cp.async.commit_group;")
#define CPA_WAIT(n)  asm volatile("cp.async.wait_group %0;" :: "n"(n))

// ---------------- init ----------------
__global__ void init_kernel(const float* __restrict__ ic_h0,
                            const float* __restrict__ ci_h0,
                            float* __restrict__ out) {
    int i = blockIdx.x * 256 + threadIdx.x;
    if (i < 16 * 256 * 32) {
        int gi = i >> 13;          // (g*4+p)
        int g  = gi >> 2;
        int k  = (i >> 5) & 255;
        const float* h0 = (g < 2) ? ic_h0 : ci_h0;
        g_H[i] = h0[(g & 1) * Dn + k];
    }
    if (i < Bn * Dn) {
        int b = i / Dn, d = i % Dn;
        float* ci = out + 32768;
        ci[((size_t)b * Tn) * 512 + d] = 0.0f;
        ci[((size_t)b * Tn + (Tn - 1)) * 512 + 256 + d] = 0.0f;
    }
    if (i < 17) g_bar[i] = 0u;
}

// ---------------- xproj SGEMM (f32x2, transposed output) ----------------
__global__ void __launch_bounds__(256) xproj_kernel(
    const float* __restrict__ X,
    const float* __restrict__ W0, const float* __restrict__ W1,
    const float* __restrict__ W2, const float* __restrict__ W3,
    const float* __restrict__ b0, const float* __restrict__ b1,
    const float* __restrict__ b2, const float* __restrict__ b3)
{
    __shared__ float As[8][128];
    __shared__ float Bs[8][128];

    const int t_  = blockIdx.y;
    const int n0  = blockIdx.x * 128;
    const int g   = n0 / 768;
    const int nc  = n0 - g * 768;
    const float* W    = (g == 0) ? W0 : (g == 1) ? W1 : (g == 2) ? W2 : W3;
    const float* bias = (g == 0) ? b0 : (g == 1) ? b1 : (g == 2) ? b2 : b3;

    const int tid  = threadIdx.x;
    const int warp = tid >> 5, lane = tid & 31;
    const int row0 = (warp & 3) * 32 + (lane >> 3) * 8;   // b
    const int col0 = (warp >> 2) * 64 + (lane & 7) * 8;

    const int am = tid >> 1, ak = (tid & 1) * 4;
    const int bk = tid >> 5, bn = (tid & 31) * 4;

    unsigned long long acc[8][4];
    #pragma unroll
    for (int i = 0; i < 8; i++)
        #pragma unroll
        for (int j = 0; j < 4; j++) acc[i][j] = 0ULL;

    for (int k0 = 0; k0 < 256; k0 += 8) {
        float4 av = __ldg((const float4*)&X[(size_t)am * (Tn * 256) + t_ * 256 + k0 + ak]);
        float4 bv = __ldg((const float4*)&W[(size_t)(k0 + bk) * 768 + nc + bn]);
        __syncthreads();
        As[ak + 0][am] = av.x; As[ak + 1][am] = av.y;
        As[ak + 2][am] = av.z; As[ak + 3][am] = av.w;
        *(float4*)&Bs[bk][bn] = bv;
        __syncthreads();

        #pragma unroll
        for (int kk = 0; kk < 8; ++kk) {
            float4 a0 = *(const float4*)&As[kk][row0];
            float4 a1 = *(const float4*)&As[kk][row0 + 4];
            ulonglong2 b01 = *(const ulonglong2*)&Bs[kk][col0];
            ulonglong2 b23 = *(const ulonglong2*)&Bs[kk][col0 + 4];
            float ar[8] = {a0.x, a0.y, a0.z, a0.w, a1.x, a1.y, a1.z, a1.w};
            #pragma unroll
            for (int i = 0; i < 8; i++) {
                unsigned long long ai = pk2(ar[i], ar[i]);
                fma2(acc[i][0], ai, b01.x);
                fma2(acc[i][1], ai, b01.y);
                fma2(acc[i][2], ai, b23.x);
                fma2(acc[i][3], ai, b23.y);
            }
        }
    }

    float c[8][8];
    #pragma unroll
    for (int i = 0; i < 8; i++) {
        up2(acc[i][0], c[i][0], c[i][1]);
        up2(acc[i][1], c[i][2], c[i][3]);
        up2(acc[i][2], c[i][4], c[i][5]);
        up2(acc[i][3], c[i][6], c[i][7]);
    }
    #pragma unroll
    for (int j = 0; j < 8; j++) {
        float bb = bias[nc + col0 + j];
        size_t base = ((size_t)(t_ * 4 + g) * 768 + nc + col0 + j) * 128 + row0;
        float4 v0 = make_float4(c[0][j] + bb, c[1][j] + bb, c[2][j] + bb, c[3][j] + bb);
        float4 v1 = make_float4(c[4][j] + bb, c[5][j] + bb, c[6][j] + bb, c[7][j] + bb);
        __stcg((float4*)&g_XP[base],     v0);
        __stcg((float4*)&g_XP[base + 4], v1);
    }
}

// ---------------- grid barrier (cumulative release via thread0 fence) ----------------
static __device__ __forceinline__ void gbar(int gi, unsigned target) {
    __syncthreads();
    if (threadIdx.x == 0) {
        __threadfence();
        atomicAdd(&g_bar[gi], 1u);
        while (*((volatile unsigned*)&g_bar[gi]) < target) { __nanosleep(32); }
        __threadfence();
    }
    __syncthreads();
}

// ---------------- scan smem layout (floats) ----------------
#define HS_OFF   0                        // 8192  : H/RH batch-slice [256][32]
#define U1_OFF   8192                     // 16384 : zr U slab [256][64]
#define U2_OFF   (U1_OFF + 16384)         // 8192  : hh U slab [256][32]
#define XP_OFF   (U2_OFF + 8192)          // 6144  : XP double buffer [2][96][32]
#define ZS_OFF   (XP_OFF + 6144)          // 1024  : z gate [32][32]
#define HSV_OFF  (ZS_OFF + 1024)          // 1024  : saved old-H [32][32]
#define SCAN_SMEM_FLOATS (HSV_OFF + 1024)
#define SCAN_SMEM_BYTES  (SCAN_SMEM_FLOATS * 4)   // 163840 B

// ---------------- persistent scan: 128 CTAs = 4 GRU x 4 bgroup x 8 colslice ----------------
__global__ void __launch_bounds__(256, 1) scan_kernel(
    const float* __restrict__ U0, const float* __restrict__ U1,
    const float* __restrict__ U2, const float* __restrict__ U3,
    const float* __restrict__ Wm, const float* __restrict__ bm,
    const float* __restrict__ Wlv, const float* __restrict__ blv,
    float* __restrict__ out)
{
    extern __shared__ float sm[];
    float* Hs   = sm + HS_OFF;
    float* U1s  = sm + U1_OFF;
    float* U2s  = sm + U2_OFF;
    float* XPd  = sm + XP_OFF;
    float* Zs   = sm + ZS_OFF;
    float* HsSv = sm + HSV_OFF;

    const int g   = blockIdx.x >> 5;
    const int pg  = (blockIdx.x >> 3) & 3;   // batch group
    const int cs  = blockIdx.x & 7;          // column slice
    const int d0  = cs * 32;
    const int gi  = g * 4 + pg;
    const int tid = threadIdx.x;
    const int b   = tid & 31;
    const int jo  = tid >> 5;                // 0..7
    const float* U = (g == 0) ? U0 : (g == 1) ? U1 : (g == 2) ? U2 : U3;

    // resident U slabs
    for (int i = tid; i < 256 * 64; i += 256) {
        int k = i >> 6, jj = i & 63;
        int col = (jj < 32) ? (d0 + jj) : (256 + d0 + jj - 32);
        U1s[i] = U[k * 768 + col];
    }
    for (int i = tid; i < 256 * 32; i += 256) {
        int k = i >> 5, jj = i & 31;
        U2s[i] = U[k * 768 + 512 + d0 + jj];
    }

    float* myH  = g_H  + gi * 8192;
    float* myRH = g_RH + gi * 8192;
    float* ci   = out + 32768;
    unsigned tgt = 0;

    const int j1 = jo * 8;     // phase1: 8 zr cols of 64
    const int j2 = jo * 4;     // phase2: 4 hh cols of 32

    // ---- prologue: stage H + XP(0) ----
    #pragma unroll
    for (int ch = 0; ch < 2; ch++) {
        #pragma unroll
        for (int r = 0; r < 4; r++)
            cpa16(Hs + ch * 4096 + (r * 256 + tid) * 4,
                  myH + ch * 4096 + (r * 256 + tid) * 4);
        CPA_COMMIT();
    }
    {
        int t0 = (g & 1) ? (Tn - 1) : 0;
        const float* xpb = g_XP + ((size_t)t0 * 4 + g) * 98304;
        #pragma unroll
        for (int i = 0; i < 3; i++) {
            int idx = i * 256 + tid;
            int cl = idx >> 3, seg = idx & 7;
            int gcol = (cl < 32) ? (d0 + cl) : (cl < 64) ? (256 + d0 + cl - 32)
                                             : (512 + d0 + cl - 64);
            cpa16(XPd + cl * 32 + seg * 4, xpb + gcol * 128 + pg * 32 + seg * 4);
        }
        CPA_COMMIT();
    }
    CPA_WAIT(0);
    __syncthreads();

    for (int s = 0; s < Tn; s++) {
        const float* XPc = XPd + (s & 1) * 3072;

        // ---- prefetch XP(s+1) ----
        {
            int sn = (s < Tn - 1) ? (s + 1) : s;
            int tn_ = (g & 1) ? (Tn - 1 - sn) : sn;
            const float* xpb = g_XP + ((size_t)tn_ * 4 + g) * 98304;
            float* dst = XPd + ((s + 1) & 1) * 3072;
            #pragma unroll
            for (int i = 0; i < 3; i++) {
                int idx = i * 256 + tid;
                int cl = idx >> 3, seg = idx & 7;
                int gcol = (cl < 32) ? (d0 + cl) : (cl < 64) ? (256 + d0 + cl - 32)
                                                 : (512 + d0 + cl - 64);
                cpa16(dst + cl * 32 + seg * 4, xpb + gcol * 128 + pg * 32 + seg * 4);
            }
            CPA_COMMIT();
        }

        // ---- phase 1: zr pre-activation ----
        unsigned long long acc[4];
        #pragma unroll
        for (int p = 0; p < 4; p++)
            acc[p] = pk2(XPc[(j1 + 2 * p) * 32 + b], XPc[(j1 + 2 * p + 1) * 32 + b]);

        CPA_WAIT(2);
        __syncthreads();
        {
            const float* u1p = U1s + j1;
            const float* hp  = Hs + b;
            #pragma unroll 8
            for (int k = 0; k < 128; k++) {
                ulonglong2 ua = *(const ulonglong2*)(u1p);
                ulonglong2 ub = *(const ulonglong2*)(u1p + 4);
                float h = *hp;
                unsigned long long hd = pk2(h, h);
                fma2(acc[0], ua.x, hd); fma2(acc[1], ua.y, hd);
                fma2(acc[2], ub.x, hd); fma2(acc[3], ub.y, hd);
                u1p += 64; hp += 32;
            }
        }
        CPA_WAIT(1);
        __syncthreads();
        {
            const float* u1p = U1s + 128 * 64 + j1;
            const float* hp  = Hs + 128 * 32 + b;
            #pragma unroll 8
            for (int k = 0; k < 128; k++) {
                ulonglong2 ua = *(const ulonglong2*)(u1p);
                ulonglong2 ub = *(const ulonglong2*)(u1p + 4);
                float h = *hp;
                unsigned long long hd = pk2(h, h);
                fma2(acc[0], ua.x, hd); fma2(acc[1], ua.y, hd);
                fma2(acc[2], ub.x, hd); fma2(acc[3], ub.y, hd);
                u1p += 64; hp += 32;
            }
        }

        // epilogue
        {
            float v[8];
            #pragma unroll
            for (int p = 0; p < 4; p++) up2(acc[p], v[2 * p], v[2 * p + 1]);
            if (jo < 4) {           // z cols (local 0..31)
                #pragma unroll
                for (int j = 0; j < 8; j++)
                    Zs[(j1 + j) * 32 + b] = sigf(v[j]);
            } else {                // r cols -> r*h -> gmem
                int jb = j1 - 32;
                #pragma unroll
                for (int j = 0; j < 8; j++) {
                    int d = d0 + jb + j;
                    float rh = sigf(v[j]) * Hs[d * 32 + b];
                    __stcg(myRH + d * 32 + b, rh);
                }
            }
            float4 hv = *(const float4*)(Hs + d0 * 32 + tid * 4);
            *(float4*)(HsSv + tid * 4) = hv;
        }
        tgt += 8;
        gbar(gi, tgt);

        // ---- stage RH (2 chunks) ----
        #pragma unroll
        for (int ch = 0; ch < 2; ch++) {
            #pragma unroll
            for (int r = 0; r < 4; r++)
                cpa16(Hs + ch * 4096 + (r * 256 + tid) * 4,
                      myRH + ch * 4096 + (r * 256 + tid) * 4);
            CPA_COMMIT();
        }

        // ---- phase 2: candidate + update ----
        unsigned long long acc2[2];
        #pragma unroll
        for (int p = 0; p < 2; p++)
            acc2[p] = pk2(XPc[(64 + j2 + 2 * p) * 32 + b],
                          XPc[(64 + j2 + 2 * p + 1) * 32 + b]);

        CPA_WAIT(1);
        __syncthreads();
        {
            const float* u2p = U2s + j2;
            const float* hp  = Hs + b;
            #pragma unroll 8
            for (int k = 0; k < 128; k++) {
                ulonglong2 u = *(const ulonglong2*)(u2p);
                float h = *hp;
                unsigned long long hd = pk2(h, h);
                fma2(acc2[0], u.x, hd); fma2(acc2[1], u.y, hd);
                u2p += 32; hp += 32;
            }
        }
        CPA_WAIT(0);
        __syncthreads();
        {
            const float* u2p = U2s + 128 * 32 + j2;
            const float* hp  = Hs + 128 * 32 + b;
            #pragma unroll 8
            for (int k = 0; k < 128; k++) {
                ulonglong2 u = *(const ulonglong2*)(u2p);
                float h = *hp;
                unsigned long long hd = pk2(h, h);
                fma2(acc2[0], u.x, hd); fma2(acc2[1], u.y, hd);
                u2p += 32; hp += 32;
            }
        }

        // epilogue: gate combine, clip, write H, ci
        {
            float w[4];
            up2(acc2[0], w[0], w[1]);
            up2(acc2[1], w[2], w[3]);
            float hn[4];
            #pragma unroll
            for (int j = 0; j < 4; j++) {
                int jl = j2 + j;
                float z  = Zs[jl * 32 + b];
                float ho = HsSv[jl * 32 + b];
                float cand = tanhfast(w[j]);
                float v = z * ho + (1.0f - z) * cand;
                hn[j] = fminf(5.0f, fmaxf(-5.0f, v));
                __stcg(myH + (d0 + jl) * 32 + b, hn[j]);
            }
            if (g >= 2 && s < Tn - 1) {
                int Bg = pg * 32 + b;
                size_t row = (g == 2)
                    ? ((size_t)Bg * Tn + s + 1) * 512 + d0 + j2
                    : ((size_t)Bg * Tn + (Tn - 2 - s)) * 512 + 256 + d0 + j2;
                __stcg((float4*)(ci + row), make_float4(hn[0], hn[1], hn[2], hn[3]));
            }
        }
        tgt += 8;
        gbar(gi, tgt);

        // ---- stage H for next step ----
        if (s < Tn - 1) {
            #pragma unroll
            for (int ch = 0; ch < 2; ch++) {
                #pragma unroll
                for (int r = 0; r < 4; r++)
                    cpa16(Hs + ch * 4096 + (r * 256 + tid) * 4,
                          myH + ch * 4096 + (r * 256 + tid) * 4);
                CPA_COMMIT();
            }
        }
    }

    // ================= fused heads (ic GRUs only) =================
    if (g < 2) {
        // cross-group barrier over the 64 ic CTAs (dedicated counter 16)
        __syncthreads();
        if (tid == 0) {
            __threadfence();
            atomicAdd(&g_bar[16], 1u);
            while (*((volatile unsigned*)&g_bar[16]) < 64u) { __nanosleep(64); }
            __threadfence();
        }
        __syncthreads();

        int rank = g * 32 + pg * 8 + cs;      // 0..63
        int b0 = rank * 2;                    // 2 batches per CTA
        float* hn0 = U1s;
        for (int i = tid; i < 2 * 512; i += 256) {
            int bb = i >> 9, kk = i & 511;
            int bat = b0 + bb;
            int pgr = bat >> 5, b32 = bat & 31;
            float v = (kk < 256) ? g_H[pgr * 8192 + kk * 32 + b32]
                                 : g_H[(4 + pgr) * 8192 + (kk - 256) * 32 + b32];
            hn0[i] = v;
        }
        __syncthreads();
        int m  = tid & 127;
        int bb = tid >> 7;
        const float* hv = hn0 + bb * 512;
        float am = bm[m], alv = blv[m];
        for (int k = 0; k < 512; k++) {
            float h = hv[k];
            am  += h * Wm [k * 128 + m];
            alv += h * Wlv[k * 128 + m];
        }
        out[(b0 + bb) * 128 + m] = am;
        out[16384 + (b0 + bb) * 128 + m] = sqrtf(expf(alv) + 1e-4f);
    }
}

// ---------------- launch ----------------
extern "C" void kernel_launch(void* const* d_in, const int* in_sizes, int n_in,
                              void* d_out, int out_size) {
    const float* data = (const float*)d_in[0];
    const float* icWf = (const float*)d_in[1];
    const float* icUf = (const float*)d_in[2];
    const float* icbf = (const float*)d_in[3];
    const float* icWb = (const float*)d_in[4];
    const float* icUb = (const float*)d_in[5];
    const float* icbb = (const float*)d_in[6];
    const float* ich0 = (const float*)d_in[7];
    const float* ciWf = (const float*)d_in[8];
    const float* ciUf = (const float*)d_in[9];
    const float* cibf = (const float*)d_in[10];
    const float* ciWb = (const float*)d_in[11];
    const float* ciUb = (const float*)d_in[12];
    const float* cibb = (const float*)d_in[13];
    const float* cih0 = (const float*)d_in[14];
    const float* Wm   = (const float*)d_in[15];
    const float* bm   = (const float*)d_in[16];
    const float* Wlv  = (const float*)d_in[17];
    const float* blv  = (const float*)d_in[18];
    float* out = (float*)d_out;

    cudaFuncSetAttribute(scan_kernel, cudaFuncAttributeMaxDynamicSharedMemorySize,
                         SCAN_SMEM_BYTES);

    init_kernel<<<512, 256>>>(ich0, cih0, out);

    dim3 grid(24, Tn);
    xproj_kernel<<<grid, 256>>>(data, icWf, icWb, ciWf, ciWb,
                                icbf, icbb, cibf, cibb);

    scan_kernel<<<128, 256, SCAN_SMEM_BYTES>>>(icUf, icUb, ciUf, ciUb,
                                               Wm, bm, Wlv, blv, out);
}